// round 5
// baseline (speedup 1.0000x reference)
#include <cuda_runtime.h>
#include <math.h>

// ---------------- problem constants ----------------
#define NN   10000      // nodes
#define NE   320000     // edges
#define FDIM 256        // F_IN == F_OUT == 256

// ---------------- device scratch (no allocs allowed) ----------------
// bitmap: 10000*10000 bits = 100,000,000 bits = 3,125,000 u32 = 781,250 uint4
#define BM_WORDS  3125000
#define BM_QUADS  781250
__device__ uint4        g_bitmap4[BM_QUADS];
__device__ int           g_rowcnt[NN];
__device__ int           g_deg[NN];
__device__ int           g_fill[NN];
__device__ int           g_rowptr[NN + 1];
__device__ float         g_dinv[NN];
__device__ unsigned char g_uniq[NE];
__device__ int           g_col[NE];
__device__ float         g_P[NN * FDIM];   // X @ W, fp32, 10.24 MB (L2-resident)

// ---------------- 1) clear per-call state ----------------
__global__ void k_clear() {
    int i = blockIdx.x * blockDim.x + threadIdx.x;
    int stride = gridDim.x * blockDim.x;
    uint4 z = make_uint4(0u, 0u, 0u, 0u);
    for (int w = i; w < BM_QUADS; w += stride) g_bitmap4[w] = z;
    if (i < NN) { g_rowcnt[i] = 0; g_deg[i] = 0; g_fill[i] = 0; }
}

// ---------------- 2) dedup edges, count degrees ----------------
__global__ void k_dedup(const int* __restrict__ src, const int* __restrict__ tgt) {
    int e = blockIdx.x * blockDim.x + threadIdx.x;
    if (e >= NE) return;
    int s = src[e], t = tgt[e];
    unsigned int bit = (unsigned int)s * (unsigned int)NN + (unsigned int)t;
    unsigned int word = bit >> 5;
    unsigned int mask = 1u << (bit & 31u);
    unsigned int* bm = reinterpret_cast<unsigned int*>(g_bitmap4);
    unsigned int old = atomicOr(&bm[word], mask);
    if (!(old & mask)) {
        g_uniq[e] = 1;
        atomicAdd(&g_rowcnt[s], 1);   // out-degree of s (row length)
        atomicAdd(&g_deg[t], 1);      // column sum contribution
    } else {
        g_uniq[e] = 0;
    }
}

// ---------------- 3) single-block exclusive scan (row_ptr) + dinv ----------------
// 1024 threads * 10 items covers 10000.
__global__ void k_scan() {
    __shared__ int sh[1024];
    int tid  = threadIdx.x;
    int base = tid * 10;
    int local[10];
    int sum = 0;
    #pragma unroll
    for (int i = 0; i < 10; i++) {
        int idx = base + i;
        int v = (idx < NN) ? g_rowcnt[idx] : 0;
        local[i] = sum;               // exclusive within thread
        sum += v;
    }
    sh[tid] = sum;
    __syncthreads();
    int total = sum;
    // Hillis-Steele inclusive scan over 1024 thread totals
    for (int off = 1; off < 1024; off <<= 1) {
        int v = (tid >= off) ? sh[tid - off] : 0;
        __syncthreads();
        sh[tid] += v;
        __syncthreads();
    }
    int excl = sh[tid] - total;
    #pragma unroll
    for (int i = 0; i < 10; i++) {
        int idx = base + i;
        if (idx < NN) g_rowptr[idx] = excl + local[i];
    }
    if (tid == 1023) g_rowptr[NN] = sh[1023];
    // d^{-1/2}: deg column-sum = unique in-edges + 1 (self loop from I)
    #pragma unroll
    for (int i = 0; i < 10; i++) {
        int idx = base + i;
        if (idx < NN) g_dinv[idx] = rsqrtf((float)(g_deg[idx] + 1));
    }
}

// ---------------- 4) scatter unique edges into CSR ----------------
__global__ void k_fill(const int* __restrict__ src, const int* __restrict__ tgt) {
    int e = blockIdx.x * blockDim.x + threadIdx.x;
    if (e >= NE) return;
    if (!g_uniq[e]) return;
    int s = src[e];
    int pos = g_rowptr[s] + atomicAdd(&g_fill[s], 1);
    g_col[pos] = tgt[e];
}

// ---------------- 5) P = X @ W  (fp32 SGEMM, BM=128 BN=64 BK=16, TM=8 TN=4) ----------------
#define GB_M 128
#define GB_N 64
#define GB_K 16
__global__ __launch_bounds__(256) void k_gemm(const float* __restrict__ X,
                                              const float* __restrict__ W) {
    __shared__ __align__(16) float As[GB_K * GB_M];  // [k][m]
    __shared__ __align__(16) float Bs[GB_K * GB_N];  // [k][n]

    int tid = threadIdx.x;
    int bm0 = blockIdx.x * GB_M;
    int bn0 = blockIdx.y * GB_N;
    int ty = tid >> 4;          // 0..15 (m dim, TM=8)
    int tx = tid & 15;          // 0..15 (n dim, TN=4)
    int m_base = ty * 8;
    int n_base = tx * 4;

    float acc[8][4];
    #pragma unroll
    for (int i = 0; i < 8; i++)
        #pragma unroll
        for (int j = 0; j < 4; j++) acc[i][j] = 0.0f;

    // A loader mapping: 512 float4 per tile, 2 per thread
    int af0 = tid;              // float4 index pass 0
    int af1 = tid + 256;        // float4 index pass 1
    // B loader mapping: 256 float4, 1 per thread
    int b_row = tid >> 4;       // 0..15 (k)
    int b_c4  = tid & 15;       // 0..15 -> col = c4*4

    for (int k0 = 0; k0 < FDIM; k0 += GB_K) {
        // load A tile (rows bm0..bm0+127, cols k0..k0+15) into As[k][m]
        #pragma unroll
        for (int pass = 0; pass < 2; pass++) {
            int f = pass ? af1 : af0;
            int row = f >> 2;         // 0..127
            int c4  = f & 3;          // 0..3
            int gr = bm0 + row;
            float4 v = make_float4(0.f, 0.f, 0.f, 0.f);
            if (gr < NN)
                v = *reinterpret_cast<const float4*>(&X[gr * FDIM + k0 + c4 * 4]);
            As[(c4 * 4 + 0) * GB_M + row] = v.x;
            As[(c4 * 4 + 1) * GB_M + row] = v.y;
            As[(c4 * 4 + 2) * GB_M + row] = v.z;
            As[(c4 * 4 + 3) * GB_M + row] = v.w;
        }
        // load B tile (rows k0..k0+15, cols bn0..bn0+63) into Bs[k][n]
        {
            float4 v = *reinterpret_cast<const float4*>(&W[(k0 + b_row) * FDIM + bn0 + b_c4 * 4]);
            *reinterpret_cast<float4*>(&Bs[b_row * GB_N + b_c4 * 4]) = v;
        }
        __syncthreads();

        #pragma unroll
        for (int kk = 0; kk < GB_K; kk++) {
            float4 a0 = *reinterpret_cast<const float4*>(&As[kk * GB_M + m_base]);
            float4 a1 = *reinterpret_cast<const float4*>(&As[kk * GB_M + m_base + 4]);
            float4 b  = *reinterpret_cast<const float4*>(&Bs[kk * GB_N + n_base]);
            float am[8] = {a0.x, a0.y, a0.z, a0.w, a1.x, a1.y, a1.z, a1.w};
            float bn[4] = {b.x, b.y, b.z, b.w};
            #pragma unroll
            for (int i = 0; i < 8; i++)
                #pragma unroll
                for (int j = 0; j < 4; j++)
                    acc[i][j] = fmaf(am[i], bn[j], acc[i][j]);
        }
        __syncthreads();
    }

    #pragma unroll
    for (int i = 0; i < 8; i++) {
        int gm = bm0 + m_base + i;
        if (gm < NN) {
            float4 v = make_float4(acc[i][0], acc[i][1], acc[i][2], acc[i][3]);
            *reinterpret_cast<float4*>(&g_P[gm * FDIM + bn0 + n_base]) = v;
        }
    }
}

// ---------------- 6) row aggregation + scaling + ReLU ----------------
// One warp per output row; 8 accumulators/lane cover 256 cols.
__global__ __launch_bounds__(256) void k_aggregate(float* __restrict__ out) {
    int warp = (blockIdx.x * blockDim.x + threadIdx.x) >> 5;
    int lane = threadIdx.x & 31;
    if (warp >= NN) return;
    int r = warp;
    float dr = g_dinv[r];

    float acc[8];
    const float* __restrict__ pr = &g_P[r * FDIM];
    #pragma unroll
    for (int j = 0; j < 8; j++) acc[j] = dr * pr[lane + 32 * j];  // identity (self-loop from I)

    int beg = g_rowptr[r];
    int end = g_rowptr[r + 1];
    for (int idx = beg; idx < end; idx++) {
        int t = g_col[idx];
        float dt = g_dinv[t];
        const float* __restrict__ p = &g_P[t * FDIM];
        #pragma unroll
        for (int j = 0; j < 8; j++) acc[j] = fmaf(dt, p[lane + 32 * j], acc[j]);
    }

    #pragma unroll
    for (int j = 0; j < 8; j++) {
        float v = dr * acc[j];
        out[r * FDIM + lane + 32 * j] = fmaxf(v, 0.0f);
    }
}

// ---------------- launch ----------------
extern "C" void kernel_launch(void* const* d_in, const int* in_sizes, int n_in,
                              void* d_out, int out_size) {
    const float* X = (const float*)d_in[0];             // [10000, 256]
    const float* W = (const float*)d_in[1];             // [256, 256]
    const int*   E = (const int*)d_in[2];               // [2, 320000] row-major
    const int* src = E;
    const int* tgt = E + NE;
    float* out = (float*)d_out;

    // 1) reset bitmap/counters
    k_clear<<<2048, 256>>>();
    // 2) dedup + degree counts
    k_dedup<<<(NE + 255) / 256, 256>>>(src, tgt);
    // 3) row_ptr scan + dinv
    k_scan<<<1, 1024>>>();
    // 4) CSR fill
    k_fill<<<(NE + 255) / 256, 256>>>(src, tgt);
    // 5) P = X @ W
    dim3 ggrid((NN + GB_M - 1) / GB_M, FDIM / GB_N);    // (79, 4)
    k_gemm<<<ggrid, 256>>>(X, W);
    // 6) aggregate + relu
    k_aggregate<<<(NN * 32 + 255) / 256, 256>>>(out);   // 1 warp per row
}

// round 8
// speedup vs baseline: 1.6884x; 1.6884x over previous
#include <cuda_runtime.h>
#include <cuda_fp16.h>
#include <math.h>
#include <stdint.h>

// ---------------- problem constants ----------------
#define NN   10000
#define NE   320000
#define FDIM 256
#define CAP  128          // fixed per-row CSR capacity (E[deg]=32, max ~60)

// bitmap: 10000*10000 bits = 3,125,000 u32 = 781,250 uint4
#define BM_QUADS 781250

// ---------------- device scratch ----------------
__device__ uint4   g_bitmap4[BM_QUADS];
__device__ int     g_rowcnt[NN];
__device__ int     g_deg[NN];
__device__ int     g_col[NN * CAP];          // 5.12 MB
__device__ float   g_P[NN * FDIM];           // X @ W, fp32 (self term)
__device__ __half  g_Ph[NN * FDIM];          // X @ W, fp16 (gather term)

__device__ __forceinline__ uint32_t tf32r(float x) {
    float r; asm("cvt.rna.tf32.f32 %0, %1;" : "=f"(r) : "f"(x));
    return __float_as_uint(r);
}

// ---------------- 1) clear per-call state ----------------
__global__ void k_clear() {
    int i = blockIdx.x * blockDim.x + threadIdx.x;
    int stride = gridDim.x * blockDim.x;
    uint4 z = make_uint4(0u, 0u, 0u, 0u);
    for (int w = i; w < BM_QUADS; w += stride) g_bitmap4[w] = z;
    for (int j = i; j < NN; j += stride) { g_rowcnt[j] = 0; g_deg[j] = 0; }
}

// ---------------- 2) dedup + degrees + CSR fill (fused), 4 edges/thread ----------------
__global__ void k_dedup_fill(const int* __restrict__ src, const int* __restrict__ tgt) {
    int i = blockIdx.x * blockDim.x + threadIdx.x;     // quad index
    if (i * 4 >= NE) return;
    int4 s4 = reinterpret_cast<const int4*>(src)[i];
    int4 t4 = reinterpret_cast<const int4*>(tgt)[i];
    int ss[4] = {s4.x, s4.y, s4.z, s4.w};
    int tt[4] = {t4.x, t4.y, t4.z, t4.w};
    unsigned int* bm = reinterpret_cast<unsigned int*>(g_bitmap4);
    #pragma unroll
    for (int j = 0; j < 4; j++) {
        int s = ss[j], t = tt[j];
        unsigned int bit  = (unsigned int)s * (unsigned int)NN + (unsigned int)t;
        unsigned int word = bit >> 5;
        unsigned int mask = 1u << (bit & 31u);
        unsigned int old  = atomicOr(&bm[word], mask);
        if (!(old & mask)) {
            int pos = atomicAdd(&g_rowcnt[s], 1);
            if (pos < CAP) g_col[s * CAP + pos] = t;
            atomicAdd(&g_deg[t], 1);
        }
    }
}

// ---------------- 3) P = X @ W via mma.sync tf32 (m16n8k8) ----------------
// CTA tile 128x128x32, 8 warps as 4(m) x 2(n), warp tile 32x64.
#define BM 128
#define BN 128
#define BK 32
#define APAD 4
#define BPAD 4

__device__ __forceinline__ void mma_tf32(float c[4],
                                         uint32_t a0, uint32_t a1, uint32_t a2, uint32_t a3,
                                         uint32_t b0, uint32_t b1) {
    asm volatile(
        "mma.sync.aligned.m16n8k8.row.col.f32.tf32.tf32.f32 "
        "{%0,%1,%2,%3}, {%4,%5,%6,%7}, {%8,%9}, {%0,%1,%2,%3};"
        : "+f"(c[0]), "+f"(c[1]), "+f"(c[2]), "+f"(c[3])
        : "r"(a0), "r"(a1), "r"(a2), "r"(a3), "r"(b0), "r"(b1));
}

__global__ __launch_bounds__(256) void k_gemm(const float* __restrict__ X,
                                              const float* __restrict__ W) {
    __shared__ __align__(16) uint32_t As[BM][BK + APAD];   // tf32 bits, row-major
    __shared__ __align__(16) uint32_t Bs[BK][BN + BPAD];   // tf32 bits, [k][n]

    int tid  = threadIdx.x;
    int wid  = tid >> 5;
    int lane = tid & 31;
    int g    = lane >> 2;           // groupID 0..7
    int t    = lane & 3;            // thread-in-group 0..3
    int bm0  = blockIdx.x * BM;
    int bn0  = blockIdx.y * BN;
    int wm   = (wid >> 1) * 32;     // warp m offset in tile
    int wn   = (wid & 1)  * 64;     // warp n offset in tile

    float acc[2][8][4];
    #pragma unroll
    for (int mt = 0; mt < 2; mt++)
        #pragma unroll
        for (int nt = 0; nt < 8; nt++)
            #pragma unroll
            for (int q = 0; q < 4; q++) acc[mt][nt][q] = 0.0f;

    for (int k0 = 0; k0 < FDIM; k0 += BK) {
        // A tile: 128x32 floats = 1024 float4, 4 per thread
        #pragma unroll
        for (int p = 0; p < 4; p++) {
            int f   = p * 256 + tid;
            int row = f >> 3;           // 0..127
            int c4  = f & 7;            // 0..7
            int gr  = bm0 + row;
            float4 v = make_float4(0.f, 0.f, 0.f, 0.f);
            if (gr < NN) v = *reinterpret_cast<const float4*>(&X[gr * FDIM + k0 + c4 * 4]);
            As[row][c4 * 4 + 0] = tf32r(v.x);
            As[row][c4 * 4 + 1] = tf32r(v.y);
            As[row][c4 * 4 + 2] = tf32r(v.z);
            As[row][c4 * 4 + 3] = tf32r(v.w);
        }
        // B tile: 32x128 floats = 1024 float4, 4 per thread
        #pragma unroll
        for (int p = 0; p < 4; p++) {
            int f   = p * 256 + tid;
            int row = f >> 5;           // 0..31 (k)
            int c4  = f & 31;           // 0..31
            float4 v = *reinterpret_cast<const float4*>(&W[(k0 + row) * FDIM + bn0 + c4 * 4]);
            Bs[row][c4 * 4 + 0] = tf32r(v.x);
            Bs[row][c4 * 4 + 1] = tf32r(v.y);
            Bs[row][c4 * 4 + 2] = tf32r(v.z);
            Bs[row][c4 * 4 + 3] = tf32r(v.w);
        }
        __syncthreads();

        #pragma unroll
        for (int ks = 0; ks < BK / 8; ks++) {
            int kb = ks * 8;
            uint32_t a[2][4];
            #pragma unroll
            for (int mt = 0; mt < 2; mt++) {
                int r0 = wm + mt * 16;
                a[mt][0] = As[r0 + g    ][kb + t    ];
                a[mt][1] = As[r0 + g + 8][kb + t    ];
                a[mt][2] = As[r0 + g    ][kb + t + 4];
                a[mt][3] = As[r0 + g + 8][kb + t + 4];
            }
            uint32_t b[8][2];
            #pragma unroll
            for (int nt = 0; nt < 8; nt++) {
                int col = wn + nt * 8 + g;
                b[nt][0] = Bs[kb + t    ][col];
                b[nt][1] = Bs[kb + t + 4][col];
            }
            #pragma unroll
            for (int mt = 0; mt < 2; mt++)
                #pragma unroll
                for (int nt = 0; nt < 8; nt++)
                    mma_tf32(acc[mt][nt], a[mt][0], a[mt][1], a[mt][2], a[mt][3],
                             b[nt][0], b[nt][1]);
        }
        __syncthreads();
    }

    // epilogue: c-frag (m16n8): rows g/g+8, cols 2t/2t+1 -> fp32 + fp16 stores
    #pragma unroll
    for (int mt = 0; mt < 2; mt++) {
        #pragma unroll
        for (int half = 0; half < 2; half++) {
            int gm = bm0 + wm + mt * 16 + g + half * 8;
            if (gm >= NN) continue;
            #pragma unroll
            for (int nt = 0; nt < 8; nt++) {
                float c0 = acc[mt][nt][half * 2 + 0];
                float c1 = acc[mt][nt][half * 2 + 1];
                int gc = bn0 + wn + nt * 8 + t * 2;
                *reinterpret_cast<float2*>(&g_P[gm * FDIM + gc]) = make_float2(c0, c1);
                *reinterpret_cast<__half2*>(&g_Ph[gm * FDIM + gc]) =
                    __float22half2_rn(make_float2(c0, c1));
            }
        }
    }
}

// ---------------- 4) aggregation + norm + ReLU (fp16 gather) ----------------
__global__ __launch_bounds__(256) void k_aggregate(float* __restrict__ out) {
    int gw   = (blockIdx.x * blockDim.x + threadIdx.x) >> 5;
    int lane = threadIdx.x & 31;
    if (gw >= NN) return;
    float dr = rsqrtf((float)(g_deg[gw] + 1));

    // self term (fp32), cols [8*lane, 8*lane+8)
    const float4* pr = reinterpret_cast<const float4*>(g_P + gw * FDIM) + lane * 2;
    float4 p0 = pr[0], p1 = pr[1];
    float a0 = dr * p0.x, a1 = dr * p0.y, a2 = dr * p0.z, a3 = dr * p0.w;
    float a4 = dr * p1.x, a5 = dr * p1.y, a6 = dr * p1.z, a7 = dr * p1.w;

    int len = g_rowcnt[gw];
    if (len > CAP) len = CAP;
    const int* cols = g_col + gw * CAP;

    #pragma unroll 2
    for (int i = 0; i < len; i++) {
        int t = cols[i];
        float dt = rsqrtf((float)(g_deg[t] + 1));
        uint4 hv = *(reinterpret_cast<const uint4*>(g_Ph + t * FDIM) + lane);
        float2 f0 = __half22float2(*reinterpret_cast<__half2*>(&hv.x));
        float2 f1 = __half22float2(*reinterpret_cast<__half2*>(&hv.y));
        float2 f2 = __half22float2(*reinterpret_cast<__half2*>(&hv.z));
        float2 f3 = __half22float2(*reinterpret_cast<__half2*>(&hv.w));
        a0 = fmaf(dt, f0.x, a0); a1 = fmaf(dt, f0.y, a1);
        a2 = fmaf(dt, f1.x, a2); a3 = fmaf(dt, f1.y, a3);
        a4 = fmaf(dt, f2.x, a4); a5 = fmaf(dt, f2.y, a5);
        a6 = fmaf(dt, f3.x, a6); a7 = fmaf(dt, f3.y, a7);
    }

    float4 o0 = make_float4(fmaxf(dr * a0, 0.f), fmaxf(dr * a1, 0.f),
                            fmaxf(dr * a2, 0.f), fmaxf(dr * a3, 0.f));
    float4 o1 = make_float4(fmaxf(dr * a4, 0.f), fmaxf(dr * a5, 0.f),
                            fmaxf(dr * a6, 0.f), fmaxf(dr * a7, 0.f));
    float4* po = reinterpret_cast<float4*>(out + gw * FDIM) + lane * 2;
    po[0] = o0; po[1] = o1;
}

// ---------------- launch ----------------
extern "C" void kernel_launch(void* const* d_in, const int* in_sizes, int n_in,
                              void* d_out, int out_size) {
    const float* X = (const float*)d_in[0];             // [10000, 256]
    const float* W = (const float*)d_in[1];             // [256, 256]
    const int*   E = (const int*)d_in[2];               // [2, 320000]
    const int* src = E;
    const int* tgt = E + NE;
    float* out = (float*)d_out;

    k_clear<<<1024, 256>>>();
    k_dedup_fill<<<(NE / 4 + 255) / 256, 256>>>(src, tgt);
    dim3 ggrid((NN + BM - 1) / BM, FDIM / BN);          // (79, 2)
    k_gemm<<<ggrid, 256>>>(X, W);
    k_aggregate<<<(NN * 32 + 255) / 256, 256>>>(out);
}

// round 9
// speedup vs baseline: 2.1108x; 1.2501x over previous
#include <cuda_runtime.h>
#include <cuda_fp16.h>
#include <math.h>
#include <stdint.h>

// ---------------- problem constants ----------------
#define NN   10000
#define NE   320000
#define FDIM 256
#define CAP  128          // fixed per-row CSR capacity (E[deg]=32, max ~60)

// bitmap: 10000*10000 bits = 3,125,000 u32 = 781,250 uint4
#define BM_QUADS 781250

// ---------------- device scratch ----------------
__device__ uint4   g_bitmap4[BM_QUADS];
__device__ int     g_rowcnt[NN];
__device__ int     g_deg[NN];
__device__ int     g_col[NN * CAP];          // 5.12 MB
__device__ float   g_Ps[NN * FDIM];          // dinv[m] * (X@W)[m], fp32 (self term)
__device__ __half  g_Ph[NN * FDIM];          // dinv[m] * (X@W)[m], fp16 (gather term)

// ---------------- 1) clear per-call state ----------------
__global__ void k_clear() {
    int i = blockIdx.x * blockDim.x + threadIdx.x;
    int stride = gridDim.x * blockDim.x;
    uint4 z = make_uint4(0u, 0u, 0u, 0u);
    for (int w = i; w < BM_QUADS; w += stride) g_bitmap4[w] = z;
    for (int j = i; j < NN; j += stride) { g_rowcnt[j] = 0; g_deg[j] = 0; }
}

// ---------------- 2) dedup + degrees + CSR fill (fused), 4 edges/thread ----------------
__global__ void k_dedup_fill(const int* __restrict__ src, const int* __restrict__ tgt) {
    int i = blockIdx.x * blockDim.x + threadIdx.x;     // quad index
    if (i * 4 >= NE) return;
    int4 s4 = reinterpret_cast<const int4*>(src)[i];
    int4 t4 = reinterpret_cast<const int4*>(tgt)[i];
    int ss[4] = {s4.x, s4.y, s4.z, s4.w};
    int tt[4] = {t4.x, t4.y, t4.z, t4.w};
    unsigned int* bm = reinterpret_cast<unsigned int*>(g_bitmap4);
    #pragma unroll
    for (int j = 0; j < 4; j++) {
        int s = ss[j], t = tt[j];
        unsigned int bit  = (unsigned int)s * (unsigned int)NN + (unsigned int)t;
        unsigned int word = bit >> 5;
        unsigned int mask = 1u << (bit & 31u);
        unsigned int old  = atomicOr(&bm[word], mask);
        if (!(old & mask)) {
            int pos = atomicAdd(&g_rowcnt[s], 1);
            if (pos < CAP) g_col[s * CAP + pos] = t;
            atomicAdd(&g_deg[t], 1);
        }
    }
}

// ---------------- 3) P = X @ W via mma.sync tf32, cp.async double-buffered ----------------
// CTA tile 128x256x32, 512 threads = 16 warps as 4(m) x 4(n), warp tile 32x64.
#define BM 128
#define BN 256
#define BK 32
#define A_LD (BK + 4)     // 36 floats/row, 16B-aligned stride
#define B_LD (BN + 8)     // 264 floats/row: (8t+g) covers all 32 banks
#define A_BYTES (BM * A_LD * 4)         // 18432
#define B_BYTES (BK * B_LD * 4)         // 33792
#define BUF_BYTES (A_BYTES + B_BYTES)   // 52224
#define SMEM_TOTAL (2 * BUF_BYTES)      // 104448

__device__ __forceinline__ uint32_t smem_u32(const void* p) {
    uint32_t a;
    asm("{ .reg .u64 t; cvta.to.shared.u64 t, %1; cvt.u32.u64 %0, t; }" : "=r"(a) : "l"(p));
    return a;
}
#define CP_ASYNC16(dst, src, szr) \
    asm volatile("cp.async.cg.shared.global [%0], [%1], 16, %2;" \
        :: "r"(dst), "l"(src), "r"(szr))
#define CP_COMMIT() asm volatile("cp.async.commit_group;" ::: "memory")
#define CP_WAIT(n)  asm volatile("cp.async.wait_group %0;" :: "n"(n) : "memory")

__device__ __forceinline__ void mma_tf32(float c[4],
                                         uint32_t a0, uint32_t a1, uint32_t a2, uint32_t a3,
                                         uint32_t b0, uint32_t b1) {
    asm volatile(
        "mma.sync.aligned.m16n8k8.row.col.f32.tf32.tf32.f32 "
        "{%0,%1,%2,%3}, {%4,%5,%6,%7}, {%8,%9}, {%0,%1,%2,%3};"
        : "+f"(c[0]), "+f"(c[1]), "+f"(c[2]), "+f"(c[3])
        : "r"(a0), "r"(a1), "r"(a2), "r"(a3), "r"(b0), "r"(b1));
}

__global__ __launch_bounds__(512, 1) void k_gemm(const float* __restrict__ X,
                                                 const float* __restrict__ W) {
    extern __shared__ char sm[];
    int tid  = threadIdx.x;
    int wid  = tid >> 5;
    int lane = tid & 31;
    int g    = lane >> 2;           // 0..7
    int t    = lane & 3;            // 0..3
    int bm0  = blockIdx.x * BM;
    int wm   = (wid >> 2) * 32;     // warp m offset
    int wn   = (wid & 3)  * 64;     // warp n offset

    // cp.async chunk mapping (16B = 4 floats each)
    // A: 128 rows x 8 chunks = 1024 chunks, 2/thread
    int a_row0 = tid >> 3,  a_c4_0 = tid & 7;                 // chunk tid
    int a_row1 = (tid + 512) >> 3, a_c4_1 = (tid + 512) & 7;  // chunk tid+512
    // B: 32 rows x 64 chunks = 2048 chunks, 4/thread

    auto issue_tile = [&](int k0, int buf) {
        uint32_t sA = smem_u32(sm + buf * BUF_BYTES);
        uint32_t sB = sA + A_BYTES;
        // A
        {
            int gr = bm0 + a_row0;
            uint32_t dst = sA + (a_row0 * A_LD + a_c4_0 * 4) * 4;
            const float* srcp = &X[(size_t)gr * FDIM + k0 + a_c4_0 * 4];
            CP_ASYNC16(dst, srcp, (gr < NN) ? 16 : 0);
            gr = bm0 + a_row1;
            dst = sA + (a_row1 * A_LD + a_c4_1 * 4) * 4;
            srcp = &X[(size_t)gr * FDIM + k0 + a_c4_1 * 4];
            CP_ASYNC16(dst, srcp, (gr < NN) ? 16 : 0);
        }
        // B
        #pragma unroll
        for (int p = 0; p < 4; p++) {
            int id  = p * 512 + tid;
            int row = id >> 6;            // 0..31 (k)
            int c4  = id & 63;            // 0..63
            uint32_t dst = sB + (row * B_LD + c4 * 4) * 4;
            const float* srcp = &W[(size_t)(k0 + row) * FDIM + c4 * 4];
            CP_ASYNC16(dst, srcp, 16);
        }
        CP_COMMIT();
    };

    float acc[2][8][4];
    #pragma unroll
    for (int mt = 0; mt < 2; mt++)
        #pragma unroll
        for (int nt = 0; nt < 8; nt++)
            #pragma unroll
            for (int q = 0; q < 4; q++) acc[mt][nt][q] = 0.0f;

    issue_tile(0, 0);

    #pragma unroll 1
    for (int ki = 0; ki < FDIM / BK; ki++) {
        int buf = ki & 1;
        if (ki + 1 < FDIM / BK) { issue_tile((ki + 1) * BK, buf ^ 1); CP_WAIT(1); }
        else                    { CP_WAIT(0); }
        __syncthreads();

        const uint32_t* As = reinterpret_cast<const uint32_t*>(sm + buf * BUF_BYTES);
        const uint32_t* Bs = reinterpret_cast<const uint32_t*>(sm + buf * BUF_BYTES + A_BYTES);

        #pragma unroll
        for (int ks = 0; ks < BK / 8; ks++) {
            int kb = ks * 8;
            uint32_t a[2][4];
            #pragma unroll
            for (int mt = 0; mt < 2; mt++) {
                int r0 = wm + mt * 16;
                a[mt][0] = As[(r0 + g    ) * A_LD + kb + t    ];
                a[mt][1] = As[(r0 + g + 8) * A_LD + kb + t    ];
                a[mt][2] = As[(r0 + g    ) * A_LD + kb + t + 4];
                a[mt][3] = As[(r0 + g + 8) * A_LD + kb + t + 4];
            }
            uint32_t b[8][2];
            #pragma unroll
            for (int nt = 0; nt < 8; nt++) {
                int col = wn + nt * 8 + g;
                b[nt][0] = Bs[(kb + t    ) * B_LD + col];
                b[nt][1] = Bs[(kb + t + 4) * B_LD + col];
            }
            #pragma unroll
            for (int mt = 0; mt < 2; mt++)
                #pragma unroll
                for (int nt = 0; nt < 8; nt++)
                    mma_tf32(acc[mt][nt], a[mt][0], a[mt][1], a[mt][2], a[mt][3],
                             b[nt][0], b[nt][1]);
        }
        __syncthreads();
    }

    // epilogue: pre-scale by dinv[m], store fp32 + fp16 copies
    #pragma unroll
    for (int mt = 0; mt < 2; mt++) {
        #pragma unroll
        for (int half = 0; half < 2; half++) {
            int gm = bm0 + wm + mt * 16 + g + half * 8;
            if (gm >= NN) continue;
            float dm = rsqrtf((float)(g_deg[gm] + 1));
            #pragma unroll
            for (int nt = 0; nt < 8; nt++) {
                float c0 = dm * acc[mt][nt][half * 2 + 0];
                float c1 = dm * acc[mt][nt][half * 2 + 1];
                int gc = wn + nt * 8 + t * 2;
                *reinterpret_cast<float2*>(&g_Ps[(size_t)gm * FDIM + gc]) = make_float2(c0, c1);
                *reinterpret_cast<__half2*>(&g_Ph[(size_t)gm * FDIM + gc]) =
                    __float22half2_rn(make_float2(c0, c1));
            }
        }
    }
}

// ---------------- 4) aggregation + ReLU (fp16 gather, pre-scaled rows) ----------------
__global__ __launch_bounds__(256) void k_aggregate(float* __restrict__ out) {
    int gw   = (blockIdx.x * blockDim.x + threadIdx.x) >> 5;
    int lane = threadIdx.x & 31;
    if (gw >= NN) return;

    // self term: acc = Ps[gw] (already dinv[gw]-scaled)
    const float4* pr = reinterpret_cast<const float4*>(g_Ps + (size_t)gw * FDIM) + lane * 2;
    float4 p0 = pr[0], p1 = pr[1];
    float a0 = p0.x, a1 = p0.y, a2 = p0.z, a3 = p0.w;
    float a4 = p1.x, a5 = p1.y, a6 = p1.z, a7 = p1.w;

    int len = g_rowcnt[gw];
    if (len > CAP) len = CAP;
    const int* cols = g_col + gw * CAP;

    int i = 0;
    // 4 neighbors per step: vector col load + HADD2 pairing, fp32 accumulate
    for (; i + 4 <= len; i += 4) {
        int4 c = *reinterpret_cast<const int4*>(cols + i);
        uint4 h0 = *(reinterpret_cast<const uint4*>(g_Ph + (size_t)c.x * FDIM) + lane);
        uint4 h1 = *(reinterpret_cast<const uint4*>(g_Ph + (size_t)c.y * FDIM) + lane);
        uint4 h2 = *(reinterpret_cast<const uint4*>(g_Ph + (size_t)c.z * FDIM) + lane);
        uint4 h3 = *(reinterpret_cast<const uint4*>(g_Ph + (size_t)c.w * FDIM) + lane);
        __half2 s0 = __hadd2(*reinterpret_cast<__half2*>(&h0.x), *reinterpret_cast<__half2*>(&h1.x));
        __half2 s1 = __hadd2(*reinterpret_cast<__half2*>(&h0.y), *reinterpret_cast<__half2*>(&h1.y));
        __half2 s2 = __hadd2(*reinterpret_cast<__half2*>(&h0.z), *reinterpret_cast<__half2*>(&h1.z));
        __half2 s3 = __hadd2(*reinterpret_cast<__half2*>(&h0.w), *reinterpret_cast<__half2*>(&h1.w));
        __half2 u0 = __hadd2(*reinterpret_cast<__half2*>(&h2.x), *reinterpret_cast<__half2*>(&h3.x));
        __half2 u1 = __hadd2(*reinterpret_cast<__half2*>(&h2.y), *reinterpret_cast<__half2*>(&h3.y));
        __half2 u2 = __hadd2(*reinterpret_cast<__half2*>(&h2.z), *reinterpret_cast<__half2*>(&h3.z));
        __half2 u3 = __hadd2(*reinterpret_cast<__half2*>(&h2.w), *reinterpret_cast<__half2*>(&h3.w));
        float2 f;
        f = __half22float2(s0); a0 += f.x; a1 += f.y;
        f = __half22float2(s1); a2 += f.x; a3 += f.y;
        f = __half22float2(s2); a4 += f.x; a5 += f.y;
        f = __half22float2(s3); a6 += f.x; a7 += f.y;
        f = __half22float2(u0); a0 += f.x; a1 += f.y;
        f = __half22float2(u1); a2 += f.x; a3 += f.y;
        f = __half22float2(u2); a4 += f.x; a5 += f.y;
        f = __half22float2(u3); a6 += f.x; a7 += f.y;
    }
    // tail
    for (; i < len; i++) {
        int c = cols[i];
        uint4 h = *(reinterpret_cast<const uint4*>(g_Ph + (size_t)c * FDIM) + lane);
        float2 f;
        f = __half22float2(*reinterpret_cast<__half2*>(&h.x)); a0 += f.x; a1 += f.y;
        f = __half22float2(*reinterpret_cast<__half2*>(&h.y)); a2 += f.x; a3 += f.y;
        f = __half22float2(*reinterpret_cast<__half2*>(&h.z)); a4 += f.x; a5 += f.y;
        f = __half22float2(*reinterpret_cast<__half2*>(&h.w)); a6 += f.x; a7 += f.y;
    }

    float dr = rsqrtf((float)(g_deg[gw] + 1));
    float4 o0 = make_float4(fmaxf(dr * a0, 0.f), fmaxf(dr * a1, 0.f),
                            fmaxf(dr * a2, 0.f), fmaxf(dr * a3, 0.f));
    float4 o1 = make_float4(fmaxf(dr * a4, 0.f), fmaxf(dr * a5, 0.f),
                            fmaxf(dr * a6, 0.f), fmaxf(dr * a7, 0.f));
    float4* po = reinterpret_cast<float4*>(out + (size_t)gw * FDIM) + lane * 2;
    po[0] = o0; po[1] = o1;
}

// ---------------- launch ----------------
extern "C" void kernel_launch(void* const* d_in, const int* in_sizes, int n_in,
                              void* d_out, int out_size) {
    const float* X = (const float*)d_in[0];             // [10000, 256]
    const float* W = (const float*)d_in[1];             // [256, 256]
    const int*   E = (const int*)d_in[2];               // [2, 320000]
    const int* src = E;
    const int* tgt = E + NE;
    float* out = (float*)d_out;

    cudaFuncSetAttribute(k_gemm, cudaFuncAttributeMaxDynamicSharedMemorySize, SMEM_TOTAL);

    k_clear<<<1024, 256>>>();
    k_dedup_fill<<<(NE / 4 + 255) / 256, 256>>>(src, tgt);
    k_gemm<<<(NN + BM - 1) / BM, 512, SMEM_TOTAL>>>(X, W);   // 79 CTAs, one wave
    k_aggregate<<<(NN * 32 + 255) / 256, 256>>>(out);
}

// round 10
// speedup vs baseline: 2.1931x; 1.0390x over previous
#include <cuda_runtime.h>
#include <cuda_fp16.h>
#include <math.h>
#include <stdint.h>

// ---------------- problem constants ----------------
#define NN   10000
#define NE   320000
#define FDIM 256
#define CAP  128          // fixed per-row CSR capacity (E[deg]=32, max ~60)

// bitmap: 10000*10000 bits = 3,125,000 u32 = 781,250 uint4
#define BM_QUADS 781250

// grid-level specialization: 79 GEMM CTAs + 69 worker CTAs = 148 = one wave
#define N_GEMM 79
#define N_WORK 69
#define NBLK   (N_GEMM + N_WORK)
#define THREADS 512

// ---------------- device scratch ----------------
__device__ uint4   g_bitmap4[BM_QUADS];
__device__ int     g_rowcnt[NN];
__device__ int     g_deg[NN];
__device__ int     g_col[NN * CAP];          // 5.12 MB
__device__ float   g_Ps[NN * FDIM];          // dinv[m] * (X@W)[m], fp32 (self term)
__device__ __half  g_Ph[NN * FDIM];          // dinv[m] * (X@W)[m], fp16 (gather term)
__device__ int     g_clear_done;             // reset by k_aggregate each call
__device__ int     g_work_done;              // reset by k_aggregate each call

// ---------------- GEMM config: 128x256x32, 16 warps 4(m)x4(n), warp 32x64 ----------------
#define BM 128
#define BN 256
#define BK 32
#define A_LD (BK + 4)     // 36 floats/row, 16B-aligned stride
#define B_LD (BN + 8)     // 264 floats/row: (8t+g) covers all 32 banks
#define A_BYTES (BM * A_LD * 4)         // 18432
#define B_BYTES (BK * B_LD * 4)         // 33792
#define BUF_BYTES (A_BYTES + B_BYTES)   // 52224
#define SMEM_TOTAL (2 * BUF_BYTES)      // 104448

__device__ __forceinline__ uint32_t smem_u32(const void* p) {
    uint32_t a;
    asm("{ .reg .u64 t; cvta.to.shared.u64 t, %1; cvt.u32.u64 %0, t; }" : "=r"(a) : "l"(p));
    return a;
}
#define CP_ASYNC16(dst, src, szr) \
    asm volatile("cp.async.cg.shared.global [%0], [%1], 16, %2;" \
        :: "r"(dst), "l"(src), "r"(szr))
#define CP_COMMIT() asm volatile("cp.async.commit_group;" ::: "memory")
#define CP_WAIT(n)  asm volatile("cp.async.wait_group %0;" :: "n"(n) : "memory")

// unbiased tf32 rounding on register operands (buy back precision vs HMMA RZ-trunc)
__device__ __forceinline__ uint32_t rna(uint32_t x) {
    float r; asm("cvt.rna.tf32.f32 %0, %1;" : "=f"(r) : "f"(__uint_as_float(x)));
    return __float_as_uint(r);
}

__device__ __forceinline__ void mma_tf32(float c[4],
                                         uint32_t a0, uint32_t a1, uint32_t a2, uint32_t a3,
                                         uint32_t b0, uint32_t b1) {
    asm volatile(
        "mma.sync.aligned.m16n8k8.row.col.f32.tf32.tf32.f32 "
        "{%0,%1,%2,%3}, {%4,%5,%6,%7}, {%8,%9}, {%0,%1,%2,%3};"
        : "+f"(c[0]), "+f"(c[1]), "+f"(c[2]), "+f"(c[3])
        : "r"(a0), "r"(a1), "r"(a2), "r"(a3), "r"(b0), "r"(b1));
}

// ---------------- fused: GEMM CTAs || (clear -> dedup+CSR) worker CTAs ----------------
__global__ __launch_bounds__(THREADS, 1) void k_fused(const float* __restrict__ X,
                                                      const float* __restrict__ W,
                                                      const int* __restrict__ src,
                                                      const int* __restrict__ tgt) {
    int tid = threadIdx.x;

    if (blockIdx.x >= N_GEMM) {
        // ================= worker role: clear, barrier, dedup+fill =================
        int gt = (blockIdx.x - N_GEMM) * THREADS + tid;
        const int nthr = N_WORK * THREADS;              // 35328

        uint4 z = make_uint4(0u, 0u, 0u, 0u);
        for (int w = gt; w < BM_QUADS; w += nthr) g_bitmap4[w] = z;
        for (int j = gt; j < NN; j += nthr) { g_rowcnt[j] = 0; g_deg[j] = 0; }
        __threadfence();
        __syncthreads();
        if (tid == 0) {
            atomicAdd(&g_clear_done, 1);
            while (*(volatile int*)&g_clear_done < N_WORK) __nanosleep(64);
        }
        __syncthreads();

        unsigned int* bm = reinterpret_cast<unsigned int*>(g_bitmap4);
        const int nq = NE / 4;                           // 80000 quads
        for (int i = gt; i < nq; i += nthr) {
            int4 s4 = reinterpret_cast<const int4*>(src)[i];
            int4 t4 = reinterpret_cast<const int4*>(tgt)[i];
            int ss[4] = {s4.x, s4.y, s4.z, s4.w};
            int tt[4] = {t4.x, t4.y, t4.z, t4.w};
            #pragma unroll
            for (int j = 0; j < 4; j++) {
                int s = ss[j], t = tt[j];
                unsigned int bit  = (unsigned int)s * (unsigned int)NN + (unsigned int)t;
                unsigned int word = bit >> 5;
                unsigned int mask = 1u << (bit & 31u);
                unsigned int old  = atomicOr(&bm[word], mask);
                if (!(old & mask)) {
                    int pos = atomicAdd(&g_rowcnt[s], 1);
                    if (pos < CAP) g_col[s * CAP + pos] = t;
                    atomicAdd(&g_deg[t], 1);
                }
            }
        }
        __threadfence();
        __syncthreads();
        if (tid == 0) atomicAdd(&g_work_done, 1);
        return;
    }

    // ================= GEMM role =================
    extern __shared__ char sm[];
    int wid  = tid >> 5;
    int lane = tid & 31;
    int g    = lane >> 2;           // 0..7
    int t    = lane & 3;            // 0..3
    int bm0  = blockIdx.x * BM;
    int wm   = (wid >> 2) * 32;     // warp m offset
    int wn   = (wid & 3)  * 64;     // warp n offset

    int a_row0 = tid >> 3,         a_c4_0 = tid & 7;
    int a_row1 = (tid + 512) >> 3, a_c4_1 = (tid + 512) & 7;

    auto issue_tile = [&](int k0, int buf) {
        uint32_t sA = smem_u32(sm + buf * BUF_BYTES);
        uint32_t sB = sA + A_BYTES;
        {
            int gr = bm0 + a_row0;
            uint32_t dst = sA + (a_row0 * A_LD + a_c4_0 * 4) * 4;
            const float* srcp = &X[(size_t)gr * FDIM + k0 + a_c4_0 * 4];
            CP_ASYNC16(dst, srcp, (gr < NN) ? 16 : 0);
            gr = bm0 + a_row1;
            dst = sA + (a_row1 * A_LD + a_c4_1 * 4) * 4;
            srcp = &X[(size_t)gr * FDIM + k0 + a_c4_1 * 4];
            CP_ASYNC16(dst, srcp, (gr < NN) ? 16 : 0);
        }
        #pragma unroll
        for (int p = 0; p < 4; p++) {
            int id  = p * 512 + tid;
            int row = id >> 6;            // 0..31 (k)
            int c4  = id & 63;            // 0..63
            uint32_t dst = sB + (row * B_LD + c4 * 4) * 4;
            const float* srcp = &W[(size_t)(k0 + row) * FDIM + c4 * 4];
            CP_ASYNC16(dst, srcp, 16);
        }
        CP_COMMIT();
    };

    float acc[2][8][4];
    #pragma unroll
    for (int mt = 0; mt < 2; mt++)
        #pragma unroll
        for (int nt = 0; nt < 8; nt++)
            #pragma unroll
            for (int q = 0; q < 4; q++) acc[mt][nt][q] = 0.0f;

    issue_tile(0, 0);

    #pragma unroll 1
    for (int ki = 0; ki < FDIM / BK; ki++) {
        int buf = ki & 1;
        if (ki + 1 < FDIM / BK) { issue_tile((ki + 1) * BK, buf ^ 1); CP_WAIT(1); }
        else                    { CP_WAIT(0); }
        __syncthreads();

        const uint32_t* As = reinterpret_cast<const uint32_t*>(sm + buf * BUF_BYTES);
        const uint32_t* Bs = reinterpret_cast<const uint32_t*>(sm + buf * BUF_BYTES + A_BYTES);

        #pragma unroll
        for (int ks = 0; ks < BK / 8; ks++) {
            int kb = ks * 8;
            uint32_t a[2][4];
            #pragma unroll
            for (int mt = 0; mt < 2; mt++) {
                int r0 = wm + mt * 16;
                a[mt][0] = rna(As[(r0 + g    ) * A_LD + kb + t    ]);
                a[mt][1] = rna(As[(r0 + g + 8) * A_LD + kb + t    ]);
                a[mt][2] = rna(As[(r0 + g    ) * A_LD + kb + t + 4]);
                a[mt][3] = rna(As[(r0 + g + 8) * A_LD + kb + t + 4]);
            }
            uint32_t b[8][2];
            #pragma unroll
            for (int nt = 0; nt < 8; nt++) {
                int col = wn + nt * 8 + g;
                b[nt][0] = rna(Bs[(kb + t    ) * B_LD + col]);
                b[nt][1] = rna(Bs[(kb + t + 4) * B_LD + col]);
            }
            #pragma unroll
            for (int mt = 0; mt < 2; mt++)
                #pragma unroll
                for (int nt = 0; nt < 8; nt++)
                    mma_tf32(acc[mt][nt], a[mt][0], a[mt][1], a[mt][2], a[mt][3],
                             b[nt][0], b[nt][1]);
        }
        __syncthreads();
    }

    // wait for workers' deg to be final, then pre-scale + store fp32/fp16 copies
    if (tid == 0)
        while (*(volatile int*)&g_work_done < N_WORK) __nanosleep(64);
    __syncthreads();
    __threadfence();

    #pragma unroll
    for (int mt = 0; mt < 2; mt++) {
        #pragma unroll
        for (int half = 0; half < 2; half++) {
            int gm = bm0 + wm + mt * 16 + g + half * 8;
            if (gm >= NN) continue;
            float dm = rsqrtf((float)(g_deg[gm] + 1));
            #pragma unroll
            for (int nt = 0; nt < 8; nt++) {
                float c0 = dm * acc[mt][nt][half * 2 + 0];
                float c1 = dm * acc[mt][nt][half * 2 + 1];
                int gc = wn + nt * 8 + t * 2;
                *reinterpret_cast<float2*>(&g_Ps[(size_t)gm * FDIM + gc]) = make_float2(c0, c1);
                *reinterpret_cast<__half2*>(&g_Ph[(size_t)gm * FDIM + gc]) =
                    __float22half2_rn(make_float2(c0, c1));
            }
        }
    }
}

// ---------------- aggregation + ReLU: 2 warps per row, fp32 accumulation ----------------
__global__ __launch_bounds__(256) void k_aggregate(float* __restrict__ out) {
    if (blockIdx.x == 0 && threadIdx.x == 0) { g_clear_done = 0; g_work_done = 0; }

    int gwarp = (blockIdx.x * blockDim.x + threadIdx.x) >> 5;   // 0..19999
    int lane  = threadIdx.x & 31;
    if (gwarp >= 2 * NN) return;
    int row = gwarp >> 1;
    int cb  = (gwarp & 1) * 128 + lane * 4;     // 4 columns per lane

    const float4 p = *reinterpret_cast<const float4*>(g_Ps + (size_t)row * FDIM + cb);
    float a0 = p.x, a1 = p.y, a2 = p.z, a3 = p.w;   // self term (pre-scaled)

    int len = g_rowcnt[row];
    if (len > CAP) len = CAP;
    const int* cols = g_col + row * CAP;

    int i = 0;
    for (; i + 4 <= len; i += 4) {
        int4 c = *reinterpret_cast<const int4*>(cols + i);
        uint2 h0 = *reinterpret_cast<const uint2*>(g_Ph + (size_t)c.x * FDIM + cb);
        uint2 h1 = *reinterpret_cast<const uint2*>(g_Ph + (size_t)c.y * FDIM + cb);
        uint2 h2 = *reinterpret_cast<const uint2*>(g_Ph + (size_t)c.z * FDIM + cb);
        uint2 h3 = *reinterpret_cast<const uint2*>(g_Ph + (size_t)c.w * FDIM + cb);
        float2 f;
        f = __half22float2(*reinterpret_cast<__half2*>(&h0.x)); a0 += f.x; a1 += f.y;
        f = __half22float2(*reinterpret_cast<__half2*>(&h0.y)); a2 += f.x; a3 += f.y;
        f = __half22float2(*reinterpret_cast<__half2*>(&h1.x)); a0 += f.x; a1 += f.y;
        f = __half22float2(*reinterpret_cast<__half2*>(&h1.y)); a2 += f.x; a3 += f.y;
        f = __half22float2(*reinterpret_cast<__half2*>(&h2.x)); a0 += f.x; a1 += f.y;
        f = __half22float2(*reinterpret_cast<__half2*>(&h2.y)); a2 += f.x; a3 += f.y;
        f = __half22float2(*reinterpret_cast<__half2*>(&h3.x)); a0 += f.x; a1 += f.y;
        f = __half22float2(*reinterpret_cast<__half2*>(&h3.y)); a2 += f.x; a3 += f.y;
    }
    for (; i < len; i++) {
        uint2 h = *reinterpret_cast<const uint2*>(g_Ph + (size_t)cols[i] * FDIM + cb);
        float2 f;
        f = __half22float2(*reinterpret_cast<__half2*>(&h.x)); a0 += f.x; a1 += f.y;
        f = __half22float2(*reinterpret_cast<__half2*>(&h.y)); a2 += f.x; a3 += f.y;
    }

    float dr = rsqrtf((float)(g_deg[row] + 1));
    *reinterpret_cast<float4*>(out + (size_t)row * FDIM + cb) =
        make_float4(fmaxf(dr * a0, 0.f), fmaxf(dr * a1, 0.f),
                    fmaxf(dr * a2, 0.f), fmaxf(dr * a3, 0.f));
}

// ---------------- launch ----------------
extern "C" void kernel_launch(void* const* d_in, const int* in_sizes, int n_in,
                              void* d_out, int out_size) {
    const float* X = (const float*)d_in[0];             // [10000, 256]
    const float* W = (const float*)d_in[1];             // [256, 256]
    const int*   E = (const int*)d_in[2];               // [2, 320000]
    const int* src = E;
    const int* tgt = E + NE;
    float* out = (float*)d_out;

    cudaFuncSetAttribute(k_fused, cudaFuncAttributeMaxDynamicSharedMemorySize, SMEM_TOTAL);

    k_fused<<<NBLK, THREADS, SMEM_TOTAL>>>(X, W, src, tgt);   // 148 CTAs = one wave
    k_aggregate<<<(2 * NN * 32) / 256, 256>>>(out);           // 2500 blocks, 2 warps/row
}